// round 2
// baseline (speedup 1.0000x reference)
#include <cuda_runtime.h>
#include <math.h>

#define BSZ   32
#define DIMN  384
#define NTOK  577
#define NPATCH 576
#define PD    768
#define DEPTH 12
#define NCLS  1000
#define EPSC  1e-5f

// ---------------- scratch (static device globals; no allocation) ----------------
__device__ float g_xp [(size_t)BSZ*NPATCH*PD];    // patchified+LN1: (B,576,768)
__device__ float g_tmp[(size_t)BSZ*NPATCH*DIMN];  // patch embed out
__device__ float g_x0 [(size_t)BSZ*NTOK*DIMN];
__device__ float g_x1 [(size_t)BSZ*NTOK*DIMN];
__device__ float g_q  [(size_t)BSZ*NTOK*DIMN];
__device__ float g_k  [(size_t)BSZ*NTOK*DIMN];
__device__ float g_v  [(size_t)BSZ*NTOK*DIMN];
__device__ float g_s  [(size_t)BSZ*NTOK*NTOK];    // scores / probs (in-place)
__device__ float g_wv [(size_t)DIMN*DIMN];        // effective V weight per layer

// ---------------- block reduction helper ----------------
__device__ __forceinline__ float block_reduce_sum(float v, float* sbuf) {
    int tid = threadIdx.x;
    sbuf[tid] = v; __syncthreads();
    for (int s = blockDim.x >> 1; s > 0; s >>= 1) {
        if (tid < s) sbuf[tid] += sbuf[tid + s];
        __syncthreads();
    }
    float r = sbuf[0]; __syncthreads();
    return r;
}

// ---------------- patchify + LN1 ----------------
// grid (576, B), block 256. threads indexed by (pr,pc) pixel; loop channels.
__global__ void ln1_patchify_kernel(const float* __restrict__ img,
                                    const float* __restrict__ g1,
                                    const float* __restrict__ b1) {
    int p = blockIdx.x, b = blockIdx.y, tid = threadIdx.x;
    int ph = p / 24, pw = p % 24;
    __shared__ float sv[PD];
    __shared__ float sred[256];
    int pr = tid >> 4, pc = tid & 15;          // 256 threads = 16x16 pixels
    float s1 = 0.f, s2 = 0.f;
    #pragma unroll
    for (int c = 0; c < 3; c++) {
        float v = img[(((size_t)b*3 + c)*384 + (ph*16 + pr))*384 + (pw*16 + pc)];
        sv[(pr*16 + pc)*3 + c] = v;
        s1 += v; s2 += v*v;
    }
    float tot  = block_reduce_sum(s1, sred);
    float tot2 = block_reduce_sum(s2, sred);
    float mean = tot / PD;
    float var  = tot2 / PD - mean*mean;
    float rs   = rsqrtf(var + EPSC);
    float* outp = g_xp + ((size_t)b*NPATCH + p)*PD;
    for (int d = tid; d < PD; d += 256)
        outp[d] = (sv[d] - mean)*rs*g1[d] + b1[d];
}

// ---------------- LN2 + cls/pos assembly ----------------
// grid (577, B), block 128
__global__ void ln2_assemble_kernel(const float* __restrict__ g2,
                                    const float* __restrict__ b2,
                                    const float* __restrict__ pos,
                                    const float* __restrict__ cls) {
    int t = blockIdx.x, b = blockIdx.y, tid = threadIdx.x;
    float* outp = g_x0 + ((size_t)b*NTOK + t)*DIMN;
    if (t == 0) {
        for (int d = tid; d < DIMN; d += 128)
            outp[d] = cls[d] + pos[d];
        return;
    }
    __shared__ float sv[DIMN];
    __shared__ float sred[128];
    const float* in = g_tmp + ((size_t)b*NPATCH + (t-1))*DIMN;
    float s1 = 0.f, s2 = 0.f;
    for (int d = tid; d < DIMN; d += 128) { float v = in[d]; sv[d] = v; s1 += v; s2 += v*v; }
    float tot  = block_reduce_sum(s1, sred);
    float tot2 = block_reduce_sum(s2, sred);
    float mean = tot / DIMN;
    float var  = tot2 / DIMN - mean*mean;
    float rs   = rsqrtf(var + EPSC);
    for (int d = tid; d < DIMN; d += 128)
        outp[d] = (sv[d] - mean)*rs*g2[d] + b2[d] + pos[(size_t)t*DIMN + d];
}

// ---------------- per-layer effective V weight ----------------
// wv_eff[d][j] = exp(lv[j][d] - max_a lv[a][d]) / (sum_a exp(lv[a][d]-max) * DIM)
// grid 384 (one block per column d), block 128
__global__ void wv_kernel(const float* __restrict__ lv) {
    int d = blockIdx.x, tid = threadIdx.x;
    __shared__ float sred[128];
    float mx = -1e30f;
    for (int a = tid; a < DIMN; a += 128) mx = fmaxf(mx, lv[(size_t)a*DIMN + d]);
    sred[tid] = mx; __syncthreads();
    for (int s = 64; s > 0; s >>= 1) { if (tid < s) sred[tid] = fmaxf(sred[tid], sred[tid+s]); __syncthreads(); }
    mx = sred[0]; __syncthreads();
    float sm = 0.f;
    for (int a = tid; a < DIMN; a += 128) sm += expf(lv[(size_t)a*DIMN + d] - mx);
    float tot = block_reduce_sum(sm, sred);
    float inv = 1.f / (tot * (float)DIMN);
    for (int j = tid; j < DIMN; j += 128)
        g_wv[(size_t)d*DIMN + j] = expf(lv[(size_t)j*DIMN + d] - mx) * inv;
}

// ---------------- column softmax over axis i (in-place on g_s) ----------------
// grid (ceil(577/256), B), block 256; thread = one column j (coalesced across j)
__global__ void colsoftmax_kernel() {
    int j = blockIdx.x*blockDim.x + threadIdx.x;
    int b = blockIdx.y;
    if (j >= NTOK) return;
    float* s = g_s + (size_t)b*NTOK*NTOK;
    float mx = -1e30f;
    for (int i = 0; i < NTOK; i++) mx = fmaxf(mx, s[(size_t)i*NTOK + j]);
    float sum = 0.f;
    for (int i = 0; i < NTOK; i++) sum += expf(s[(size_t)i*NTOK + j] - mx);
    float inv = 1.f / sum;
    for (int i = 0; i < NTOK; i++) {
        size_t id = (size_t)i*NTOK + j;
        s[id] = expf(s[id] - mx) * inv;
    }
}

// ---------------- SGEMM 128x128x16, 256 threads, 8x8 per thread ----------------
// TB: B operand is N-major (row-major NxK, i.e. use B^T)
// EPI: 0 plain, 1 +bias[n], 2 *alpha, 3 residual blend: 0.5*(acc - E1) + 0.5*E2
#define GBM 128
#define GBN 128
#define GBK 16

template<bool TB, int EPI>
__global__ void __launch_bounds__(256)
gemm_kernel(const float* __restrict__ A, int lda, long sA,
            const float* __restrict__ B, int ldb, long sB,
            float* __restrict__ C, int ldc, long sC,
            int M, int N, int K, float alpha,
            const float* __restrict__ bias,
            const float* __restrict__ E1, long sE1,
            const float* __restrict__ E2, long sE2) {
    int z = blockIdx.z;
    A += (size_t)z * sA;
    B += (size_t)z * sB;
    C += (size_t)z * sC;
    if (EPI == 3) { E1 += (size_t)z * sE1; E2 += (size_t)z * sE2; }

    __shared__ float As[GBK][GBM + 4];
    __shared__ float Bs[GBK][GBN + 4];

    int tid = threadIdx.x;
    int m0 = blockIdx.y * GBM, n0 = blockIdx.x * GBN;
    int tm = (tid >> 4) << 3;   // (tid/16)*8
    int tn = (tid & 15) << 3;   // (tid%16)*8

    float acc[8][8];
    #pragma unroll
    for (int i = 0; i < 8; i++)
        #pragma unroll
        for (int j = 0; j < 8; j++) acc[i][j] = 0.f;

    for (int k0 = 0; k0 < K; k0 += GBK) {
        // load A tile (BM x BK), store transposed As[k][m]
        #pragma unroll
        for (int it = 0; it < 8; it++) {
            int e = tid + it*256;
            int m = e >> 4, kk = e & 15;
            int gm = m0 + m, gk = k0 + kk;
            As[kk][m] = (gm < M && gk < K) ? A[(long)gm*lda + gk] : 0.f;
        }
        if (!TB) {
            #pragma unroll
            for (int it = 0; it < 8; it++) {
                int e = tid + it*256;
                int kk = e >> 7, n = e & 127;
                int gk = k0 + kk, gn = n0 + n;
                Bs[kk][n] = (gk < K && gn < N) ? B[(long)gk*ldb + gn] : 0.f;
            }
        } else {
            #pragma unroll
            for (int it = 0; it < 8; it++) {
                int e = tid + it*256;
                int n = e >> 4, kk = e & 15;
                int gn = n0 + n, gk = k0 + kk;
                Bs[kk][n] = (gn < N && gk < K) ? B[(long)gn*ldb + gk] : 0.f;
            }
        }
        __syncthreads();
        #pragma unroll
        for (int kk = 0; kk < GBK; kk++) {
            float a[8], bb[8];
            *(float4*)&a[0]  = *(const float4*)&As[kk][tm];
            *(float4*)&a[4]  = *(const float4*)&As[kk][tm + 4];
            *(float4*)&bb[0] = *(const float4*)&Bs[kk][tn];
            *(float4*)&bb[4] = *(const float4*)&Bs[kk][tn + 4];
            #pragma unroll
            for (int i = 0; i < 8; i++)
                #pragma unroll
                for (int j = 0; j < 8; j++)
                    acc[i][j] += a[i] * bb[j];
        }
        __syncthreads();
    }

    #pragma unroll
    for (int i = 0; i < 8; i++) {
        int gm = m0 + tm + i;
        if (gm >= M) continue;
        #pragma unroll
        for (int j = 0; j < 8; j++) {
            int gn = n0 + tn + j;
            if (gn >= N) continue;
            float r = acc[i][j];
            long idx = (long)gm*ldc + gn;
            if (EPI == 1) r += bias[gn];
            else if (EPI == 2) r *= alpha;
            else if (EPI == 3) r = 0.5f*(r - E1[idx]) + 0.5f*E2[idx];
            C[idx] = r;
        }
    }
}

// ---------------- classifier head: out[b,:] = x0[b,0,:] @ Wh + bh ----------------
__global__ void head_kernel(const float* __restrict__ Wh,
                            const float* __restrict__ bh,
                            float* __restrict__ out) {
    int b = blockIdx.x, tid = threadIdx.x;
    __shared__ float sx[DIMN];
    for (int d = tid; d < DIMN; d += 256)
        sx[d] = g_x0[(size_t)b*NTOK*DIMN + d];
    __syncthreads();
    for (int n = tid; n < NCLS; n += 256) {
        float acc = bh[n];
        #pragma unroll 4
        for (int kk = 0; kk < DIMN; kk++)
            acc += sx[kk] * Wh[(size_t)kk*NCLS + n];
        out[(size_t)b*NCLS + n] = acc;
    }
}

// ---------------- launch ----------------
extern "C" void kernel_launch(void* const* d_in, const int* in_sizes, int n_in,
                              void* d_out, int out_size) {
    const float* img    = (const float*)d_in[0];
    const float* ln1_g  = (const float*)d_in[1];
    const float* ln1_b  = (const float*)d_in[2];
    const float* Wp     = (const float*)d_in[3];
    const float* bp     = (const float*)d_in[4];
    const float* ln2_g  = (const float*)d_in[5];
    const float* ln2_b  = (const float*)d_in[6];
    const float* pos    = (const float*)d_in[7];
    const float* cls    = (const float*)d_in[8];
    const float* wk     = (const float*)d_in[9];
    const float* wq     = (const float*)d_in[10];
    const float* wv_raw = (const float*)d_in[11];
    const float* Wh     = (const float*)d_in[12];
    const float* bh     = (const float*)d_in[13];
    float* out = (float*)d_out;

    float *xp, *tmp, *x0, *x1, *q, *k, *v, *s, *wv;
    cudaGetSymbolAddress((void**)&xp,  g_xp);
    cudaGetSymbolAddress((void**)&tmp, g_tmp);
    cudaGetSymbolAddress((void**)&x0,  g_x0);
    cudaGetSymbolAddress((void**)&x1,  g_x1);
    cudaGetSymbolAddress((void**)&q,   g_q);
    cudaGetSymbolAddress((void**)&k,   g_k);
    cudaGetSymbolAddress((void**)&v,   g_v);
    cudaGetSymbolAddress((void**)&s,   g_s);
    cudaGetSymbolAddress((void**)&wv,  g_wv);

    const int Mtok = BSZ * NTOK;      // 18464
    const int Mpat = BSZ * NPATCH;    // 18432
    const float scale = 1.f / sqrtf((float)NTOK);

    // 1) patchify + LN1
    ln1_patchify_kernel<<<dim3(NPATCH, BSZ), 256>>>(img, ln1_g, ln1_b);

    // 2) patch embed GEMM (+bias): tmp = xp @ Wp + bp
    gemm_kernel<false,1><<<dim3(DIMN/GBN, Mpat/GBM, 1), 256>>>(
        xp, PD, 0, Wp, DIMN, 0, tmp, DIMN, 0,
        Mpat, DIMN, PD, 0.f, bp, nullptr, 0, nullptr, 0);

    // 3) LN2 + cls/pos -> x0
    ln2_assemble_kernel<<<dim3(NTOK, BSZ), 128>>>(ln2_g, ln2_b, pos, cls);

    float* cur = x0;
    float* nxt = x1;
    const dim3 gQKV(DIMN/GBN, (Mtok + GBM - 1)/GBM, 1);     // (3,145,1)
    const dim3 gSC((NTOK + GBN - 1)/GBN, (NTOK + GBM - 1)/GBM, BSZ);  // (5,5,32)
    const dim3 gOUT(DIMN/GBN, (NTOK + GBM - 1)/GBM, BSZ);   // (3,5,32)
    const long sTok = (long)NTOK * DIMN;
    const long sSc  = (long)NTOK * NTOK;

    for (int l = 0; l < DEPTH; l++) {
        const float* lq = wq + (size_t)l*DIMN*DIMN;
        const float* lk = wk + (size_t)l*DIMN*DIMN;
        const float* lv = wv_raw + (size_t)l*DIMN*DIMN;

        // effective V weight
        wv_kernel<<<DIMN, 128>>>(lv);

        // q, k, v projections (flattened over batch*tokens)
        gemm_kernel<false,0><<<gQKV, 256>>>(cur, DIMN, 0, lq, DIMN, 0, q, DIMN, 0,
            Mtok, DIMN, DIMN, 0.f, nullptr, nullptr, 0, nullptr, 0);
        gemm_kernel<false,0><<<gQKV, 256>>>(cur, DIMN, 0, lk, DIMN, 0, k, DIMN, 0,
            Mtok, DIMN, DIMN, 0.f, nullptr, nullptr, 0, nullptr, 0);
        gemm_kernel<false,0><<<gQKV, 256>>>(cur, DIMN, 0, wv, DIMN, 0, v, DIMN, 0,
            Mtok, DIMN, DIMN, 0.f, nullptr, nullptr, 0, nullptr, 0);

        // scores[b] = scale * q_b @ k_b^T   (batched NT)
        gemm_kernel<true,2><<<gSC, 256>>>(q, DIMN, sTok, k, DIMN, sTok, s, NTOK, sSc,
            NTOK, NTOK, DIMN, scale, nullptr, nullptr, 0, nullptr, 0);

        // softmax over axis i (columns), in place
        colsoftmax_kernel<<<dim3((NTOK + 255)/256, BSZ), 256>>>();

        // x_new = 0.5*(probs @ v - v) + 0.5*x   (batched NN, fused epilogue)
        gemm_kernel<false,3><<<gOUT, 256>>>(s, NTOK, sSc, v, DIMN, sTok, nxt, DIMN, sTok,
            NTOK, DIMN, NTOK, 0.f, nullptr, v, sTok, cur, sTok);

        float* t2 = cur; cur = nxt; nxt = t2;
    }
    // after 12 layers cur == x0 again; head reads g_x0 directly
    head_kernel<<<BSZ, 256>>>(Wh, bh, out);
}

// round 3
// speedup vs baseline: 1.5048x; 1.5048x over previous
#include <cuda_runtime.h>
#include <math.h>
#include <stdint.h>

#define BSZ   32
#define DIMN  384
#define NTOK  577
#define NPATCH 576
#define PD    768
#define DEPTH 12
#define NCLS  1000
#define EPSC  1e-5f

// ---------------- scratch (static device globals; no allocation) ----------------
__device__ float g_xp [(size_t)BSZ*NPATCH*PD];
__device__ float g_tmp[(size_t)BSZ*NPATCH*DIMN];
__device__ float g_x0 [(size_t)BSZ*NTOK*DIMN];
__device__ float g_x1 [(size_t)BSZ*NTOK*DIMN];
__device__ float g_q  [(size_t)BSZ*NTOK*DIMN];
__device__ float g_k  [(size_t)BSZ*NTOK*DIMN];
__device__ float g_v  [(size_t)BSZ*NTOK*DIMN];
__device__ float g_s  [(size_t)BSZ*NTOK*NTOK];
__device__ float g_wv [(size_t)DIMN*DIMN];

// ---------------- helpers ----------------
__device__ __forceinline__ float block_reduce_sum(float v, float* sbuf) {
    int tid = threadIdx.x;
    sbuf[tid] = v; __syncthreads();
    for (int s = blockDim.x >> 1; s > 0; s >>= 1) {
        if (tid < s) sbuf[tid] += sbuf[tid + s];
        __syncthreads();
    }
    float r = sbuf[0]; __syncthreads();
    return r;
}

__device__ __forceinline__ void split_tf32(float f, uint32_t& big, uint32_t& sml) {
    uint32_t b;
    asm("cvt.rna.tf32.f32 %0, %1;" : "=r"(b) : "f"(f));
    float r = f - __uint_as_float(b);
    uint32_t s;
    asm("cvt.rna.tf32.f32 %0, %1;" : "=r"(s) : "f"(r));
    big = b; sml = s;
}

__device__ __forceinline__ void mma_tf32(float* c, const uint32_t* a, const uint32_t* b) {
    asm volatile(
        "mma.sync.aligned.m16n8k8.row.col.f32.tf32.tf32.f32 "
        "{%0,%1,%2,%3},{%4,%5,%6,%7},{%8,%9},{%0,%1,%2,%3};\n"
        : "+f"(c[0]), "+f"(c[1]), "+f"(c[2]), "+f"(c[3])
        : "r"(a[0]), "r"(a[1]), "r"(a[2]), "r"(a[3]), "r"(b[0]), "r"(b[1]));
}

// ---------------- patchify + LN1 ----------------
__global__ void ln1_patchify_kernel(const float* __restrict__ img,
                                    const float* __restrict__ g1,
                                    const float* __restrict__ b1) {
    int p = blockIdx.x, b = blockIdx.y, tid = threadIdx.x;
    int ph = p / 24, pw = p % 24;
    __shared__ float sv[PD];
    __shared__ float sred[256];
    int pr = tid >> 4, pc = tid & 15;
    float s1 = 0.f, s2 = 0.f;
    #pragma unroll
    for (int c = 0; c < 3; c++) {
        float v = img[(((size_t)b*3 + c)*384 + (ph*16 + pr))*384 + (pw*16 + pc)];
        sv[(pr*16 + pc)*3 + c] = v;
        s1 += v; s2 += v*v;
    }
    float tot  = block_reduce_sum(s1, sred);
    float tot2 = block_reduce_sum(s2, sred);
    float mean = tot / PD;
    float var  = tot2 / PD - mean*mean;
    float rs   = rsqrtf(var + EPSC);
    float* outp = g_xp + ((size_t)b*NPATCH + p)*PD;
    for (int d = tid; d < PD; d += 256)
        outp[d] = (sv[d] - mean)*rs*g1[d] + b1[d];
}

// ---------------- LN2 + cls/pos assembly ----------------
__global__ void ln2_assemble_kernel(const float* __restrict__ g2,
                                    const float* __restrict__ b2,
                                    const float* __restrict__ pos,
                                    const float* __restrict__ cls) {
    int t = blockIdx.x, b = blockIdx.y, tid = threadIdx.x;
    float* outp = g_x0 + ((size_t)b*NTOK + t)*DIMN;
    if (t == 0) {
        for (int d = tid; d < DIMN; d += 128)
            outp[d] = cls[d] + pos[d];
        return;
    }
    __shared__ float sv[DIMN];
    __shared__ float sred[128];
    const float* in = g_tmp + ((size_t)b*NPATCH + (t-1))*DIMN;
    float s1 = 0.f, s2 = 0.f;
    for (int d = tid; d < DIMN; d += 128) { float v = in[d]; sv[d] = v; s1 += v; s2 += v*v; }
    float tot  = block_reduce_sum(s1, sred);
    float tot2 = block_reduce_sum(s2, sred);
    float mean = tot / DIMN;
    float var  = tot2 / DIMN - mean*mean;
    float rs   = rsqrtf(var + EPSC);
    for (int d = tid; d < DIMN; d += 128)
        outp[d] = (sv[d] - mean)*rs*g2[d] + b2[d] + pos[(size_t)t*DIMN + d];
}

// ---------------- per-layer effective V weight ----------------
__global__ void wv_kernel(const float* __restrict__ lv) {
    int d = blockIdx.x, tid = threadIdx.x;
    __shared__ float sred[128];
    float mx = -1e30f;
    for (int a = tid; a < DIMN; a += 128) mx = fmaxf(mx, lv[(size_t)a*DIMN + d]);
    sred[tid] = mx; __syncthreads();
    for (int s = 64; s > 0; s >>= 1) { if (tid < s) sred[tid] = fmaxf(sred[tid], sred[tid+s]); __syncthreads(); }
    mx = sred[0]; __syncthreads();
    float sm = 0.f;
    for (int a = tid; a < DIMN; a += 128) sm += expf(lv[(size_t)a*DIMN + d] - mx);
    float tot = block_reduce_sum(sm, sred);
    float inv = 1.f / (tot * (float)DIMN);
    for (int j = tid; j < DIMN; j += 128)
        g_wv[(size_t)d*DIMN + j] = expf(lv[(size_t)j*DIMN + d] - mx) * inv;
}

// ---------------- column softmax over axis i (in-place on g_s) ----------------
__global__ void colsoftmax_kernel() {
    int j = blockIdx.x*blockDim.x + threadIdx.x;
    int b = blockIdx.y;
    if (j >= NTOK) return;
    float* s = g_s + (size_t)b*NTOK*NTOK;
    float mx = -1e30f;
    for (int i = 0; i < NTOK; i++) mx = fmaxf(mx, s[(size_t)i*NTOK + j]);
    float sum = 0.f;
    for (int i = 0; i < NTOK; i++) sum += expf(s[(size_t)i*NTOK + j] - mx);
    float inv = 1.f / sum;
    for (int i = 0; i < NTOK; i++) {
        size_t id = (size_t)i*NTOK + j;
        s[id] = expf(s[id] - mx) * inv;
    }
}

// ================= tensor-core GEMM: 3xTF32, 128x128x16, 8 warps =================
// TB: B operand is N-major (row-major NxK, i.e. use B^T)
// EPI: 0 plain, 1 +bias[n], 2 *alpha, 3 residual blend: 0.5*(acc - E1) + 0.5*E2
#define TBM 128
#define TBN 128
#define TBK 16
#define LDAS (TBM + 4)
#define LDBS (TBN + 4)

template<bool TB, int EPI>
__global__ void __launch_bounds__(256)
tgemm_kernel(const float* __restrict__ A, int lda, long sA,
             const float* __restrict__ B, int ldb, long sB,
             float* __restrict__ C, int ldc, long sC,
             int M, int N, int K, float alpha,
             const float* __restrict__ bias,
             const float* __restrict__ E1, long sE1,
             const float* __restrict__ E2, long sE2) {
    int z = blockIdx.z;
    A += (size_t)z * sA;
    B += (size_t)z * sB;
    C += (size_t)z * sC;
    if (EPI == 3) { E1 += (size_t)z * sE1; E2 += (size_t)z * sE2; }

    __shared__ float As[2][TBK][LDAS];
    __shared__ float Bs[2][TBK][LDBS];

    int tid  = threadIdx.x;
    int lane = tid & 31;
    int warp = tid >> 5;
    int wm   = warp >> 2;       // 0..1  -> m offset wm*64
    int wn   = warp & 3;        // 0..3  -> n offset wn*32
    int m0 = blockIdx.y * TBM, n0 = blockIdx.x * TBN;

    float acc[4][4][4];
    #pragma unroll
    for (int i = 0; i < 4; i++)
        #pragma unroll
        for (int j = 0; j < 4; j++)
            #pragma unroll
            for (int r = 0; r < 4; r++) acc[i][j][r] = 0.f;

    float ra[8], rb[8];

    auto gload = [&](int k0) {
        #pragma unroll
        for (int it = 0; it < 8; it++) {
            int e = tid + it*256;
            int m = e >> 4, kk = e & 15;
            int gm = m0 + m, gk = k0 + kk;
            ra[it] = (gm < M && gk < K) ? A[(long)gm*lda + gk] : 0.f;
        }
        if (!TB) {
            #pragma unroll
            for (int it = 0; it < 8; it++) {
                int e = tid + it*256;
                int kk = e >> 7, n = e & 127;
                int gk = k0 + kk, gn = n0 + n;
                rb[it] = (gk < K && gn < N) ? B[(long)gk*ldb + gn] : 0.f;
            }
        } else {
            #pragma unroll
            for (int it = 0; it < 8; it++) {
                int e = tid + it*256;
                int n = e >> 4, kk = e & 15;
                int gn = n0 + n, gk = k0 + kk;
                rb[it] = (gn < N && gk < K) ? B[(long)gn*ldb + gk] : 0.f;
            }
        }
    };
    auto sstore = [&](int buf) {
        #pragma unroll
        for (int it = 0; it < 8; it++) {
            int e = tid + it*256;
            As[buf][e & 15][e >> 4] = ra[it];
        }
        if (!TB) {
            #pragma unroll
            for (int it = 0; it < 8; it++) {
                int e = tid + it*256;
                Bs[buf][e >> 7][e & 127] = rb[it];
            }
        } else {
            #pragma unroll
            for (int it = 0; it < 8; it++) {
                int e = tid + it*256;
                Bs[buf][e & 15][e >> 4] = rb[it];
            }
        }
    };

    auto compute = [&](int buf) {
        #pragma unroll
        for (int kc = 0; kc < 2; kc++) {
            int kb = kc * 8 + (lane & 3);
            uint32_t abig[4][4], asml[4][4];
            #pragma unroll
            for (int mt = 0; mt < 4; mt++) {
                int mr = wm*64 + mt*16 + (lane >> 2);
                split_tf32(As[buf][kb    ][mr    ], abig[mt][0], asml[mt][0]);
                split_tf32(As[buf][kb    ][mr + 8], abig[mt][1], asml[mt][1]);
                split_tf32(As[buf][kb + 4][mr    ], abig[mt][2], asml[mt][2]);
                split_tf32(As[buf][kb + 4][mr + 8], abig[mt][3], asml[mt][3]);
            }
            uint32_t bbig[4][2], bsml[4][2];
            #pragma unroll
            for (int nt = 0; nt < 4; nt++) {
                int nc = wn*32 + nt*8 + (lane >> 2);
                split_tf32(Bs[buf][kb    ][nc], bbig[nt][0], bsml[nt][0]);
                split_tf32(Bs[buf][kb + 4][nc], bbig[nt][1], bsml[nt][1]);
            }
            #pragma unroll
            for (int mt = 0; mt < 4; mt++)
                #pragma unroll
                for (int nt = 0; nt < 4; nt++) {
                    mma_tf32(acc[mt][nt], abig[mt], bbig[nt]);
                    mma_tf32(acc[mt][nt], abig[mt], bsml[nt]);
                    mma_tf32(acc[mt][nt], asml[mt], bbig[nt]);
                }
        }
    };

    int nk = (K + TBK - 1) / TBK;
    gload(0);
    sstore(0);
    __syncthreads();
    int buf = 0;
    for (int t = 0; t < nk; t++) {
        if (t + 1 < nk) gload((t + 1) * TBK);
        compute(buf);
        if (t + 1 < nk) {
            sstore(buf ^ 1);
            __syncthreads();
            buf ^= 1;
        }
    }

    // epilogue
    #pragma unroll
    for (int mt = 0; mt < 4; mt++) {
        #pragma unroll
        for (int nt = 0; nt < 4; nt++) {
            #pragma unroll
            for (int r = 0; r < 4; r++) {
                int gm = m0 + wm*64 + mt*16 + (lane >> 2) + ((r >= 2) ? 8 : 0);
                int gn = n0 + wn*32 + nt*8 + 2*(lane & 3) + (r & 1);
                if (gm >= M || gn >= N) continue;
                float v = acc[mt][nt][r];
                long idx = (long)gm*ldc + gn;
                if (EPI == 1) v += bias[gn];
                else if (EPI == 2) v *= alpha;
                else if (EPI == 3) v = 0.5f*(v - E1[idx]) + 0.5f*E2[idx];
                C[idx] = v;
            }
        }
    }
}

// ---------------- classifier head ----------------
__global__ void head_kernel(const float* __restrict__ Wh,
                            const float* __restrict__ bh,
                            float* __restrict__ out) {
    int b = blockIdx.x, tid = threadIdx.x;
    __shared__ float sx[DIMN];
    for (int d = tid; d < DIMN; d += 256)
        sx[d] = g_x0[(size_t)b*NTOK*DIMN + d];
    __syncthreads();
    for (int n = tid; n < NCLS; n += 256) {
        float acc = bh[n];
        #pragma unroll 4
        for (int kk = 0; kk < DIMN; kk++)
            acc += sx[kk] * Wh[(size_t)kk*NCLS + n];
        out[(size_t)b*NCLS + n] = acc;
    }
}

// ---------------- launch ----------------
extern "C" void kernel_launch(void* const* d_in, const int* in_sizes, int n_in,
                              void* d_out, int out_size) {
    const float* img    = (const float*)d_in[0];
    const float* ln1_g  = (const float*)d_in[1];
    const float* ln1_b  = (const float*)d_in[2];
    const float* Wp     = (const float*)d_in[3];
    const float* bp     = (const float*)d_in[4];
    const float* ln2_g  = (const float*)d_in[5];
    const float* ln2_b  = (const float*)d_in[6];
    const float* pos    = (const float*)d_in[7];
    const float* cls    = (const float*)d_in[8];
    const float* wk     = (const float*)d_in[9];
    const float* wq     = (const float*)d_in[10];
    const float* wv_raw = (const float*)d_in[11];
    const float* Wh     = (const float*)d_in[12];
    const float* bh     = (const float*)d_in[13];
    float* out = (float*)d_out;

    float *xp, *tmp, *x0, *x1, *q, *k, *v, *s, *wv;
    cudaGetSymbolAddress((void**)&xp,  g_xp);
    cudaGetSymbolAddress((void**)&tmp, g_tmp);
    cudaGetSymbolAddress((void**)&x0,  g_x0);
    cudaGetSymbolAddress((void**)&x1,  g_x1);
    cudaGetSymbolAddress((void**)&q,   g_q);
    cudaGetSymbolAddress((void**)&k,   g_k);
    cudaGetSymbolAddress((void**)&v,   g_v);
    cudaGetSymbolAddress((void**)&s,   g_s);
    cudaGetSymbolAddress((void**)&wv,  g_wv);

    const int Mtok = BSZ * NTOK;      // 18464
    const int Mpat = BSZ * NPATCH;    // 18432
    const float scale = 1.f / sqrtf((float)NTOK);

    ln1_patchify_kernel<<<dim3(NPATCH, BSZ), 256>>>(img, ln1_g, ln1_b);

    tgemm_kernel<false,1><<<dim3(DIMN/TBN, Mpat/TBM, 1), 256>>>(
        xp, PD, 0, Wp, DIMN, 0, tmp, DIMN, 0,
        Mpat, DIMN, PD, 0.f, bp, nullptr, 0, nullptr, 0);

    ln2_assemble_kernel<<<dim3(NTOK, BSZ), 128>>>(ln2_g, ln2_b, pos, cls);

    float* cur = x0;
    float* nxt = x1;
    const dim3 gQKV(DIMN/TBN, (Mtok + TBM - 1)/TBM, 1);
    const dim3 gSC((NTOK + TBN - 1)/TBN, (NTOK + TBM - 1)/TBM, BSZ);
    const dim3 gOUT(DIMN/TBN, (NTOK + TBM - 1)/TBM, BSZ);
    const long sTok = (long)NTOK * DIMN;
    const long sSc  = (long)NTOK * NTOK;

    for (int l = 0; l < DEPTH; l++) {
        const float* lq = wq + (size_t)l*DIMN*DIMN;
        const float* lk = wk + (size_t)l*DIMN*DIMN;
        const float* lv = wv_raw + (size_t)l*DIMN*DIMN;

        wv_kernel<<<DIMN, 128>>>(lv);

        tgemm_kernel<false,0><<<gQKV, 256>>>(cur, DIMN, 0, lq, DIMN, 0, q, DIMN, 0,
            Mtok, DIMN, DIMN, 0.f, nullptr, nullptr, 0, nullptr, 0);
        tgemm_kernel<false,0><<<gQKV, 256>>>(cur, DIMN, 0, lk, DIMN, 0, k, DIMN, 0,
            Mtok, DIMN, DIMN, 0.f, nullptr, nullptr, 0, nullptr, 0);
        tgemm_kernel<false,0><<<gQKV, 256>>>(cur, DIMN, 0, wv, DIMN, 0, v, DIMN, 0,
            Mtok, DIMN, DIMN, 0.f, nullptr, nullptr, 0, nullptr, 0);

        tgemm_kernel<true,2><<<gSC, 256>>>(q, DIMN, sTok, k, DIMN, sTok, s, NTOK, sSc,
            NTOK, NTOK, DIMN, scale, nullptr, nullptr, 0, nullptr, 0);

        colsoftmax_kernel<<<dim3((NTOK + 255)/256, BSZ), 256>>>();

        tgemm_kernel<false,3><<<gOUT, 256>>>(s, NTOK, sSc, v, DIMN, sTok, nxt, DIMN, sTok,
            NTOK, DIMN, NTOK, 0.f, nullptr, v, sTok, cur, sTok);

        float* t2 = cur; cur = nxt; nxt = t2;
    }
    head_kernel<<<BSZ, 256>>>(Wh, bh, out);
}

// round 5
// speedup vs baseline: 2.3658x; 1.5721x over previous
#include <cuda_runtime.h>
#include <cuda_bf16.h>
#include <math.h>
#include <stdint.h>

#define BSZ    32
#define DIMN   384
#define NTOK   577
#define NTOKP  640
#define NPATCH 576
#define PD     768
#define DEPTH  12
#define NCLS   1000
#define EPSC   1e-5f
#define MTOK   (BSZ*NTOK)    // 18464
#define MPAT   (BSZ*NPATCH)  // 18432

// ===================== scratch (static device globals) =====================
__device__ float g_tmp[(size_t)MPAT*DIMN];
__device__ float g_x0 [(size_t)MTOK*DIMN];
__device__ float g_x1 [(size_t)MTOK*DIMN];
__device__ float g_v  [(size_t)MTOK*DIMN];
__device__ float g_s  [(size_t)BSZ*NTOK*NTOK];
__device__ float g_wvstat[2*DIMN];

#define PLANE(name, sz) __device__ __align__(16) __nv_bfloat16 name[(size_t)(sz)]
PLANE(g_xph, (size_t)MPAT*PD);   PLANE(g_xpl, (size_t)MPAT*PD);
PLANE(g_wpth, DIMN*PD);          PLANE(g_wptl, DIMN*PD);
PLANE(g_w1h, DIMN*DIMN);         PLANE(g_w1l, DIMN*DIMN);     // lq^T
PLANE(g_w2h, DIMN*DIMN);         PLANE(g_w2l, DIMN*DIMN);     // lk^T
PLANE(g_wvth, DIMN*DIMN);        PLANE(g_wvtl, DIMN*DIMN);    // wv^T
PLANE(g_x0h, (size_t)MTOK*DIMN); PLANE(g_x0l, (size_t)MTOK*DIMN);
PLANE(g_x1h, (size_t)MTOK*DIMN); PLANE(g_x1l, (size_t)MTOK*DIMN);
PLANE(g_qh,  (size_t)MTOK*DIMN); PLANE(g_ql,  (size_t)MTOK*DIMN);
PLANE(g_kh,  (size_t)MTOK*DIMN); PLANE(g_kl,  (size_t)MTOK*DIMN);
PLANE(g_vth, (size_t)BSZ*DIMN*NTOKP); PLANE(g_vtl, (size_t)BSZ*DIMN*NTOKP);
PLANE(g_ph,  (size_t)BSZ*NTOK*NTOKP); PLANE(g_pl,  (size_t)BSZ*NTOK*NTOKP);

// ===================== small helpers =====================
__device__ __forceinline__ void bsplit(float f, __nv_bfloat16& h, __nv_bfloat16& l) {
    h = __float2bfloat16(f);
    l = __float2bfloat16(f - __bfloat162float(h));
}

__device__ __forceinline__ float block_reduce_sum(float v, float* sbuf) {
    int tid = threadIdx.x;
    sbuf[tid] = v; __syncthreads();
    for (int s = blockDim.x >> 1; s > 0; s >>= 1) {
        if (tid < s) sbuf[tid] += sbuf[tid + s];
        __syncthreads();
    }
    float r = sbuf[0]; __syncthreads();
    return r;
}

__device__ __forceinline__ uint32_t smem_u32(const void* p) {
    uint32_t a;
    asm("{ .reg .u64 t; cvta.to.shared.u64 t, %1; cvt.u32.u64 %0, t; }" : "=r"(a) : "l"(p));
    return a;
}

__device__ __forceinline__ void mma_bf16(float* c, const uint32_t* a, const uint32_t* b) {
    asm volatile(
        "mma.sync.aligned.m16n8k16.row.col.f32.bf16.bf16.f32 "
        "{%0,%1,%2,%3},{%4,%5,%6,%7},{%8,%9},{%0,%1,%2,%3};\n"
        : "+f"(c[0]), "+f"(c[1]), "+f"(c[2]), "+f"(c[3])
        : "r"(a[0]), "r"(a[1]), "r"(a[2]), "r"(a[3]), "r"(b[0]), "r"(b[1]));
}

__device__ __forceinline__ void ldsm4(uint32_t* r, uint32_t addr) {
    asm volatile("ldmatrix.sync.aligned.m8n8.x4.shared.b16 {%0,%1,%2,%3}, [%4];"
                 : "=r"(r[0]), "=r"(r[1]), "=r"(r[2]), "=r"(r[3]) : "r"(addr));
}

__device__ __forceinline__ void cpasync16(uint32_t dst, const void* src, int srcsize) {
    asm volatile("cp.async.cg.shared.global [%0], [%1], 16, %2;"
                 :: "r"(dst), "l"(src), "r"(srcsize) : "memory");
}
#define CP_COMMIT() asm volatile("cp.async.commit_group;" ::: "memory")
template<int NG> __device__ __forceinline__ void cp_wait() {
    asm volatile("cp.async.wait_group %0;" :: "n"(NG) : "memory");
}

// smem stage layout: 4 planes (Ah, Al, Bh, Bl), each 128 rows x 32 bf16, pitch 40 bf16 (80 B)
#define SPITCH    40
#define PLANE_B   (128 * SPITCH * 2)     // 10240
#define STAGE_B   (4 * PLANE_B)          // 40960
#define SMEM_BYTES (2 * STAGE_B)         // 81920 (epilogue reuses: 128*132*4 = 67584)

// ===================== bf16 split-plane tensor GEMM (mma.sync) =====================
// C[M,N] = A[M,K] * B[N,K]^T ; A/B bf16 hi/lo planes, K-major, K multiple of 32, 16B-aligned rows.
// EPI: 0 fp32 plain, 1 fp32+bias, 2 fp32*alpha, 3 planes only, 4: fp32 0.5*(v-E1)+0.5*E2 + planes
template<int EPI>
__global__ void __launch_bounds__(256)
tc_gemm(const __nv_bfloat16* __restrict__ Ah, const __nv_bfloat16* __restrict__ Al,
        int lda, long sA,
        const __nv_bfloat16* __restrict__ Bh, const __nv_bfloat16* __restrict__ Bl,
        int ldb, long sB,
        float* __restrict__ C, int ldc, long sC,
        int M, int N, int K, float alpha,
        const float* __restrict__ bias,
        const float* __restrict__ E1, long sE1,
        const float* __restrict__ E2, long sE2,
        __nv_bfloat16* __restrict__ Ph, __nv_bfloat16* __restrict__ Pl,
        int ldp, long sP)
{
    extern __shared__ char smem[];
    uint32_t sbase = smem_u32(smem);
    int tid = threadIdx.x, lane = tid & 31, wid = tid >> 5;
    int wm = wid >> 2, wn = wid & 3;       // warp tile: 64x32 at (wm*64, wn*32)
    int z = blockIdx.z;
    Ah += (size_t)z * sA; Al += (size_t)z * sA;
    Bh += (size_t)z * sB; Bl += (size_t)z * sB;
    if (EPI != 3) C += (size_t)z * sC;
    if (EPI == 4) { E1 += (size_t)z * sE1; E2 += (size_t)z * sE2; }
    if (EPI == 3 || EPI == 4) { Ph += (size_t)z * sP; Pl += (size_t)z * sP; }
    int m0 = blockIdx.y * 128, n0 = blockIdx.x * 128;

    float acc[4][4][4];
    #pragma unroll
    for (int i = 0; i < 4; i++)
        #pragma unroll
        for (int j = 0; j < 4; j++)
            #pragma unroll
            for (int r = 0; r < 4; r++) acc[i][j][r] = 0.f;

    // per-lane ldmatrix row/col offsets
    int arow = (lane & 7) + ((lane >> 3) & 1) * 8;   // + mt*16 + wm*64
    int acol = (lane >> 4) * 8;                      // + s*16
    int brow = (lane & 7) + ((lane >> 4) ? 8 : 0);   // + np*16 + wn*32
    int bcol = ((lane >> 3) & 1) * 8;

    auto stage_load = [&](int t) {
        uint32_t sb = sbase + (uint32_t)(t & 1) * STAGE_B;
        long k0 = (long)t * 32;
        #pragma unroll
        for (int it = 0; it < 2; it++) {
            int e = tid + it * 256;                  // 0..511
            int r = e >> 2, c4 = e & 3;
            uint32_t d = sb + (uint32_t)(r * (SPITCH*2) + c4 * 16);
            int gm = m0 + r;
            bool okA = gm < M;
            const char* pA = (const char*)(Ah + (long)(okA ? gm : 0) * lda + k0) + c4 * 16;
            const char* pAl2 = (const char*)(Al + (long)(okA ? gm : 0) * lda + k0) + c4 * 16;
            cpasync16(d,             pA,   okA ? 16 : 0);
            cpasync16(d + PLANE_B,   pAl2, okA ? 16 : 0);
            int gn = n0 + r;
            bool okB = gn < N;
            const char* pB = (const char*)(Bh + (long)(okB ? gn : 0) * ldb + k0) + c4 * 16;
            const char* pBl2 = (const char*)(Bl + (long)(okB ? gn : 0) * ldb + k0) + c4 * 16;
            cpasync16(d + 2*PLANE_B, pB,   okB ? 16 : 0);
            cpasync16(d + 3*PLANE_B, pBl2, okB ? 16 : 0);
        }
        CP_COMMIT();
    };

    auto compute = [&](int buf) {
        uint32_t sb = sbase + (uint32_t)buf * STAGE_B;
        uint32_t aAh = sb +               (uint32_t)((wm*64 + arow) * (SPITCH*2) + acol*2);
        uint32_t aAl = aAh + PLANE_B;
        uint32_t aBh = sb + 2*PLANE_B +   (uint32_t)((wn*32 + brow) * (SPITCH*2) + bcol*2);
        uint32_t aBl = aBh + PLANE_B;
        #pragma unroll
        for (int s = 0; s < 2; s++) {
            uint32_t koff = (uint32_t)(s * 16 * 2);
            uint32_t ah[4][4], al[4][4];
            #pragma unroll
            for (int mt = 0; mt < 4; mt++) {
                uint32_t ro = (uint32_t)(mt * 16 * (SPITCH*2)) + koff;
                ldsm4(ah[mt], aAh + ro);
                ldsm4(al[mt], aAl + ro);
            }
            uint32_t bh2[2][4], bl2[2][4];
            #pragma unroll
            for (int np = 0; np < 2; np++) {
                uint32_t ro = (uint32_t)(np * 16 * (SPITCH*2)) + koff;
                ldsm4(bh2[np], aBh + ro);
                ldsm4(bl2[np], aBl + ro);
            }
            #pragma unroll
            for (int mt = 0; mt < 4; mt++)
                #pragma unroll
                for (int nt = 0; nt < 4; nt++) {
                    const uint32_t* bh_ = &bh2[nt >> 1][(nt & 1) * 2];
                    const uint32_t* bl_ = &bl2[nt >> 1][(nt & 1) * 2];
                    mma_bf16(acc[mt][nt], ah[mt], bh_);
                    mma_bf16(acc[mt][nt], ah[mt], bl_);
                    mma_bf16(acc[mt][nt], al[mt], bh_);
                }
        }
    };

    int nk = K / 32;
    stage_load(0);
    for (int t = 0; t < nk; t++) {
        if (t + 1 < nk) { stage_load(t + 1); cp_wait<1>(); }
        else            { cp_wait<0>(); }
        __syncthreads();
        compute(t & 1);
        __syncthreads();
    }

    // epilogue: regs -> smem (pitch 132 floats) -> gmem coalesced
    float* sst = (float*)smem;
    int g = lane >> 2, tq = lane & 3;
    #pragma unroll
    for (int mt = 0; mt < 4; mt++)
        #pragma unroll
        for (int nt = 0; nt < 4; nt++)
            #pragma unroll
            for (int r = 0; r < 4; r++) {
                int m = wm*64 + mt*16 + g + ((r >= 2) ? 8 : 0);
                int n = wn*32 + nt*8 + 2*tq + (r & 1);
                sst[m * 132 + n] = acc[mt][nt][r];
            }
    __syncthreads();
    for (int e = tid; e < 16384; e += 256) {
        int r = e >> 7, c = e & 127;
        int gm = m0 + r, gn = n0 + c;
        if (gm >= M || gn >= N) continue;
        float val = sst[r * 132 + c];
        if (EPI == 0) {
            C[(long)gm * ldc + gn] = val;
        } else if (EPI == 1) {
            C[(long)gm * ldc + gn] = val + bias[gn];
        } else if (EPI == 2) {
            C[(long)gm * ldc + gn] = val * alpha;
        } else if (EPI == 3) {
            __nv_bfloat16 h, l; bsplit(val, h, l);
            Ph[(long)gm * ldp + gn] = h; Pl[(long)gm * ldp + gn] = l;
        } else {
            long ix = (long)gm * ldc + gn;
            float v2 = 0.5f * (val - E1[ix]) + 0.5f * E2[ix];
            C[ix] = v2;
            __nv_bfloat16 h, l; bsplit(v2, h, l);
            Ph[(long)gm * ldp + gn] = h; Pl[(long)gm * ldp + gn] = l;
        }
    }
}

// ===================== elementwise kernels =====================
__global__ void ln1_patchify_kernel(const float* __restrict__ img,
                                    const float* __restrict__ g1,
                                    const float* __restrict__ b1) {
    int p = blockIdx.x, b = blockIdx.y, tid = threadIdx.x;
    int phh = p / 24, pw = p % 24;
    __shared__ float sv[PD];
    __shared__ float sred[256];
    int pr = tid >> 4, pc = tid & 15;
    float s1 = 0.f, s2 = 0.f;
    #pragma unroll
    for (int c = 0; c < 3; c++) {
        float v = img[(((size_t)b*3 + c)*384 + (phh*16 + pr))*384 + (pw*16 + pc)];
        sv[(pr*16 + pc)*3 + c] = v;
        s1 += v; s2 += v*v;
    }
    float tot  = block_reduce_sum(s1, sred);
    float tot2 = block_reduce_sum(s2, sred);
    float mean = tot / PD;
    float var  = tot2 / PD - mean*mean;
    float rs   = rsqrtf(var + EPSC);
    size_t base = ((size_t)b*NPATCH + p)*PD;
    for (int d = tid; d < PD; d += 256) {
        float f = (sv[d] - mean)*rs*g1[d] + b1[d];
        __nv_bfloat16 h, l; bsplit(f, h, l);
        g_xph[base + d] = h; g_xpl[base + d] = l;
    }
}

__global__ void ln2_assemble_kernel(const float* __restrict__ g2,
                                    const float* __restrict__ b2,
                                    const float* __restrict__ pos,
                                    const float* __restrict__ cls) {
    int t = blockIdx.x, b = blockIdx.y, tid = threadIdx.x;
    size_t base = ((size_t)b*NTOK + t)*DIMN;
    if (t == 0) {
        for (int d = tid; d < DIMN; d += 128) {
            float f = cls[d] + pos[d];
            g_x0[base + d] = f;
            __nv_bfloat16 h, l; bsplit(f, h, l);
            g_x0h[base + d] = h; g_x0l[base + d] = l;
        }
        return;
    }
    __shared__ float sv[DIMN];
    __shared__ float sred[128];
    const float* in = g_tmp + ((size_t)b*NPATCH + (t-1))*DIMN;
    float s1 = 0.f, s2 = 0.f;
    for (int d = tid; d < DIMN; d += 128) { float v = in[d]; sv[d] = v; s1 += v; s2 += v*v; }
    float tot  = block_reduce_sum(s1, sred);
    float tot2 = block_reduce_sum(s2, sred);
    float mean = tot / DIMN;
    float var  = tot2 / DIMN - mean*mean;
    float rs   = rsqrtf(var + EPSC);
    for (int d = tid; d < DIMN; d += 128) {
        float f = (sv[d] - mean)*rs*g2[d] + b2[d] + pos[(size_t)t*DIMN + d];
        g_x0[base + d] = f;
        __nv_bfloat16 h, l; bsplit(f, h, l);
        g_x0h[base + d] = h; g_x0l[base + d] = l;
    }
}

__global__ void wvstat_kernel(const float* __restrict__ lv) {
    int k = blockIdx.x, tid = threadIdx.x;
    __shared__ float sred[128];
    float mx = -1e30f;
    for (int a = tid; a < DIMN; a += 128) mx = fmaxf(mx, lv[(size_t)a*DIMN + k]);
    sred[tid] = mx; __syncthreads();
    for (int s = 64; s > 0; s >>= 1) { if (tid < s) sred[tid] = fmaxf(sred[tid], sred[tid+s]); __syncthreads(); }
    mx = sred[0]; __syncthreads();
    float sm = 0.f;
    for (int a = tid; a < DIMN; a += 128) sm += __expf(lv[(size_t)a*DIMN + k] - mx);
    float tot = block_reduce_sum(sm, sred);
    if (tid == 0) {
        g_wvstat[k] = mx;
        g_wvstat[DIMN + k] = 1.f / (tot * (float)DIMN);
    }
}

__global__ void wvT_kernel(const float* __restrict__ lv) {
    int n = blockIdx.x, tid = threadIdx.x;
    for (int k = tid; k < DIMN; k += 128) {
        float f = __expf(lv[(size_t)n*DIMN + k] - g_wvstat[k]) * g_wvstat[DIMN + k];
        __nv_bfloat16 h, l; bsplit(f, h, l);
        g_wvth[(size_t)n*DIMN + k] = h; g_wvtl[(size_t)n*DIMN + k] = l;
    }
}

// fp32 [R,C] (pitch, batch stride) -> bf16 hi/lo planes [C, Rpad] (zero-padded cols r>=R)
__global__ void transconv_kernel(const float* __restrict__ src, int R, int Cc, int pitch, long sZ,
                                 __nv_bfloat16* __restrict__ dh, __nv_bfloat16* __restrict__ dl,
                                 int Rpad, long dZ) {
    __shared__ float tile[32][33];
    int z = blockIdx.z;
    src += (size_t)z * sZ; dh += (size_t)z * dZ; dl += (size_t)z * dZ;
    int rb = blockIdx.x * 32, cb = blockIdx.y * 32;
    int tx = threadIdx.x, ty = threadIdx.y;   // 32 x 8
    #pragma unroll
    for (int i = 0; i < 4; i++) {
        int r = rb + ty + i*8, c = cb + tx;
        tile[ty + i*8][tx] = (r < R && c < Cc) ? src[(long)r*pitch + c] : 0.f;
    }
    __syncthreads();
    #pragma unroll
    for (int i = 0; i < 4; i++) {
        int dr = cb + ty + i*8;
        int dc = rb + tx;
        if (dr < Cc && dc < Rpad) {
            float f = tile[tx][ty + i*8];
            __nv_bfloat16 h, l; bsplit(f, h, l);
            dh[(long)dr*Rpad + dc] = h; dl[(long)dr*Rpad + dc] = l;
        }
    }
}

// column softmax over axis i of scores -> probs planes [i][640] (pad cols zeroed)
__global__ void colsoftmax_kernel() {
    int j = blockIdx.x * blockDim.x + threadIdx.x;
    int b = blockIdx.y;
    if (j >= NTOKP) return;
    __nv_bfloat16* ph = g_ph + (size_t)b*NTOK*NTOKP;
    __nv_bfloat16* pl = g_pl + (size_t)b*NTOK*NTOKP;
    __nv_bfloat16 z16 = __float2bfloat16(0.f);
    if (j >= NTOK) {
        for (int i = 0; i < NTOK; i++) {
            ph[(size_t)i*NTOKP + j] = z16;
            pl[(size_t)i*NTOKP + j] = z16;
        }
        return;
    }
    const float* s = g_s + (size_t)b*NTOK*NTOK;
    float m = -1e30f, sum = 0.f;
    for (int i = 0; i < NTOK; i++) {
        float v = s[(size_t)i*NTOK + j];
        float nm = fmaxf(m, v);
        sum = sum * __expf(m - nm) + __expf(v - nm);
        m = nm;
    }
    float inv = 1.f / sum;
    for (int i = 0; i < NTOK; i++) {
        float p = __expf(s[(size_t)i*NTOK + j] - m) * inv;
        __nv_bfloat16 h, l; bsplit(p, h, l);
        ph[(size_t)i*NTOKP + j] = h;
        pl[(size_t)i*NTOKP + j] = l;
    }
}

__global__ void head_kernel(const float* __restrict__ Wh,
                            const float* __restrict__ bh,
                            float* __restrict__ out) {
    int b = blockIdx.x, tid = threadIdx.x;
    __shared__ float sx[DIMN];
    for (int d = tid; d < DIMN; d += 256)
        sx[d] = g_x0[(size_t)b*NTOK*DIMN + d];
    __syncthreads();
    for (int n = tid; n < NCLS; n += 256) {
        float acc = bh[n];
        #pragma unroll 4
        for (int kk = 0; kk < DIMN; kk++)
            acc += sx[kk] * Wh[(size_t)kk*NCLS + n];
        out[(size_t)b*NCLS + n] = acc;
    }
}

// ===================== launch =====================
extern "C" void kernel_launch(void* const* d_in, const int* in_sizes, int n_in,
                              void* d_out, int out_size) {
    const float* img    = (const float*)d_in[0];
    const float* ln1_g  = (const float*)d_in[1];
    const float* ln1_b  = (const float*)d_in[2];
    const float* Wp     = (const float*)d_in[3];
    const float* bp     = (const float*)d_in[4];
    const float* ln2_g  = (const float*)d_in[5];
    const float* ln2_b  = (const float*)d_in[6];
    const float* pos    = (const float*)d_in[7];
    const float* cls    = (const float*)d_in[8];
    const float* wk     = (const float*)d_in[9];
    const float* wq     = (const float*)d_in[10];
    const float* wv_raw = (const float*)d_in[11];
    const float* Wh     = (const float*)d_in[12];
    const float* bh     = (const float*)d_in[13];
    float* out = (float*)d_out;

    cudaFuncSetAttribute(tc_gemm<0>, cudaFuncAttributeMaxDynamicSharedMemorySize, SMEM_BYTES);
    cudaFuncSetAttribute(tc_gemm<1>, cudaFuncAttributeMaxDynamicSharedMemorySize, SMEM_BYTES);
    cudaFuncSetAttribute(tc_gemm<2>, cudaFuncAttributeMaxDynamicSharedMemorySize, SMEM_BYTES);
    cudaFuncSetAttribute(tc_gemm<3>, cudaFuncAttributeMaxDynamicSharedMemorySize, SMEM_BYTES);
    cudaFuncSetAttribute(tc_gemm<4>, cudaFuncAttributeMaxDynamicSharedMemorySize, SMEM_BYTES);

    float *tmp, *x0f, *x1f, *vf, *sf;
    cudaGetSymbolAddress((void**)&tmp, g_tmp);
    cudaGetSymbolAddress((void**)&x0f, g_x0);
    cudaGetSymbolAddress((void**)&x1f, g_x1);
    cudaGetSymbolAddress((void**)&vf,  g_v);
    cudaGetSymbolAddress((void**)&sf,  g_s);
    __nv_bfloat16 *xph,*xpl,*wpth,*wptl,*w1h,*w1l,*w2h,*w2l,*wvth,*wvtl;
    __nv_bfloat16 *x0h,*x0l,*x1h,*x1l,*qh,*ql,*kh,*kl,*vth,*vtl,*pph,*ppl;
    cudaGetSymbolAddress((void**)&xph, g_xph);   cudaGetSymbolAddress((void**)&xpl, g_xpl);
    cudaGetSymbolAddress((void**)&wpth, g_wpth); cudaGetSymbolAddress((void**)&wptl, g_wptl);
    cudaGetSymbolAddress((void**)&w1h, g_w1h);   cudaGetSymbolAddress((void**)&w1l, g_w1l);
    cudaGetSymbolAddress((void**)&w2h, g_w2h);   cudaGetSymbolAddress((void**)&w2l, g_w2l);
    cudaGetSymbolAddress((void**)&wvth, g_wvth); cudaGetSymbolAddress((void**)&wvtl, g_wvtl);
    cudaGetSymbolAddress((void**)&x0h, g_x0h);   cudaGetSymbolAddress((void**)&x0l, g_x0l);
    cudaGetSymbolAddress((void**)&x1h, g_x1h);   cudaGetSymbolAddress((void**)&x1l, g_x1l);
    cudaGetSymbolAddress((void**)&qh, g_qh);     cudaGetSymbolAddress((void**)&ql, g_ql);
    cudaGetSymbolAddress((void**)&kh, g_kh);     cudaGetSymbolAddress((void**)&kl, g_kl);
    cudaGetSymbolAddress((void**)&vth, g_vth);   cudaGetSymbolAddress((void**)&vtl, g_vtl);
    cudaGetSymbolAddress((void**)&pph, g_ph);    cudaGetSymbolAddress((void**)&ppl, g_pl);

    const float scale = 1.f / sqrtf((float)NTOK);
    const long sTok = (long)NTOK * DIMN;
    const long sSc  = (long)NTOK * NTOK;
    const long sP   = (long)NTOK * NTOKP;
    const long sVT  = (long)DIMN * NTOKP;

    // 1) patchify + LN1 -> xp planes
    ln1_patchify_kernel<<<dim3(NPATCH, BSZ), 256>>>(img, ln1_g, ln1_b);
    // 2) Wp^T planes
    transconv_kernel<<<dim3(PD/32, DIMN/32, 1), dim3(32,8)>>>(Wp, PD, DIMN, DIMN, 0, wpth, wptl, PD, 0);
    // 3) patch embed: tmp = xp @ Wp + bp
    tc_gemm<1><<<dim3(DIMN/128, MPAT/128, 1), 256, SMEM_BYTES>>>(
        xph, xpl, PD, 0, wpth, wptl, PD, 0, tmp, DIMN, 0,
        MPAT, DIMN, PD, 0.f, bp, nullptr, 0, nullptr, 0, nullptr, nullptr, 0, 0);
    // 4) LN2 + cls/pos -> x0 (fp32 + planes)
    ln2_assemble_kernel<<<dim3(NTOK, BSZ), 128>>>(ln2_g, ln2_b, pos, cls);

    float* cur = x0f; __nv_bfloat16 *curh = x0h, *curl = x0l;
    float* nxt = x1f; __nv_bfloat16 *nxth = x1h, *nxtl = x1l;
    const dim3 gQKV(DIMN/128, (MTOK + 127)/128, 1);           // (3,145)
    const dim3 gSC((NTOK + 127)/128, (NTOK + 127)/128, BSZ);  // (5,5,32)
    const dim3 gOUT(DIMN/128, (NTOK + 127)/128, BSZ);         // (3,5,32)

    for (int l = 0; l < DEPTH; l++) {
        const float* lq = wq + (size_t)l*DIMN*DIMN;
        const float* lk = wk + (size_t)l*DIMN*DIMN;
        const float* lv = wv_raw + (size_t)l*DIMN*DIMN;

        wvstat_kernel<<<DIMN, 128>>>(lv);
        wvT_kernel<<<DIMN, 128>>>(lv);
        transconv_kernel<<<dim3(DIMN/32, DIMN/32, 1), dim3(32,8)>>>(lq, DIMN, DIMN, DIMN, 0, w1h, w1l, DIMN, 0);
        transconv_kernel<<<dim3(DIMN/32, DIMN/32, 1), dim3(32,8)>>>(lk, DIMN, DIMN, DIMN, 0, w2h, w2l, DIMN, 0);

        // q, k: planes only
        tc_gemm<3><<<gQKV, 256, SMEM_BYTES>>>(
            curh, curl, DIMN, 0, w1h, w1l, DIMN, 0, nullptr, 0, 0,
            MTOK, DIMN, DIMN, 0.f, nullptr, nullptr, 0, nullptr, 0, qh, ql, DIMN, 0);
        tc_gemm<3><<<gQKV, 256, SMEM_BYTES>>>(
            curh, curl, DIMN, 0, w2h, w2l, DIMN, 0, nullptr, 0, 0,
            MTOK, DIMN, DIMN, 0.f, nullptr, nullptr, 0, nullptr, 0, kh, kl, DIMN, 0);
        // v: fp32
        tc_gemm<0><<<gQKV, 256, SMEM_BYTES>>>(
            curh, curl, DIMN, 0, wvth, wvtl, DIMN, 0, vf, DIMN, 0,
            MTOK, DIMN, DIMN, 0.f, nullptr, nullptr, 0, nullptr, 0, nullptr, nullptr, 0, 0);
        // v^T planes (batched, padded to 640)
        transconv_kernel<<<dim3(NTOKP/32, DIMN/32, BSZ), dim3(32,8)>>>(
            vf, NTOK, DIMN, DIMN, sTok, vth, vtl, NTOKP, sVT);
        // scores = scale * q @ k^T  (batched)
        tc_gemm<2><<<gSC, 256, SMEM_BYTES>>>(
            qh, ql, DIMN, sTok, kh, kl, DIMN, sTok, sf, NTOK, sSc,
            NTOK, NTOK, DIMN, scale, nullptr, nullptr, 0, nullptr, 0, nullptr, nullptr, 0, 0);
        // column softmax -> probs planes
        colsoftmax_kernel<<<dim3((NTOKP + 255)/256, BSZ), 256>>>();
        // x_new = 0.5*(probs @ v - v) + 0.5*x  (fp32 + planes)
        tc_gemm<4><<<gOUT, 256, SMEM_BYTES>>>(
            pph, ppl, NTOKP, sP, vth, vtl, NTOKP, sVT, nxt, DIMN, sTok,
            NTOK, DIMN, NTOKP, 0.f, nullptr, vf, sTok, cur, sTok, nxth, nxtl, DIMN, sTok);

        float* tf = cur; cur = nxt; nxt = tf;
        __nv_bfloat16* th = curh; curh = nxth; nxth = th;
        __nv_bfloat16* tl = curl; curl = nxtl; nxtl = tl;
    }
    // after 12 layers cur == x0
    head_kernel<<<BSZ, 256>>>(Wh, bh, out);
}